// round 2
// baseline (speedup 1.0000x reference)
#include <cuda_runtime.h>
#include <math.h>

#define FULLMASK 0xffffffffu
typedef unsigned long long u64;

static constexpr int NL     = 2048;
static constexpr int NQ     = 16384;
static constexpr int NB     = 2;
static constexpr int H      = 64;
static constexpr int PH     = 256;
static constexpr int COUT   = 3;
static constexpr int KCAP   = 32;
static constexpr int CAP    = 192;
static constexpr int THREADS= 128;
static constexpr int WARPS  = 4;
static constexpr int NBLOCK = 444;   // 148 SMs x 3 CTAs

// ---- dynamic shared memory layout (float offsets) ----
static constexpr int OFF_COORD = 0;         // 4096
static constexpr int OFF_WE0   = 4096;      // 256   [4][64]
static constexpr int OFF_BE0   = 4352;      // 64
static constexpr int OFF_WE1   = 4416;      // 4096  [64][64]  (16B aligned)
static constexpr int OFF_BE1   = 8512;      // 64
static constexpr int OFF_WE2   = 8576;      // 4096  (16B aligned)
static constexpr int OFF_BE2   = 12672;     // 64
static constexpr int OFF_WSW0  = 12736;     // 32
static constexpr int OFF_BSW0  = 12768;     // 16
static constexpr int OFF_WSW1  = 12784;     // 32
static constexpr int OFF_BSW1  = 12816;     // 2 (+2 pad)
static constexpr int OFF_WP1   = 12820;     // 768  [256][3]
static constexpr int OFF_BP1   = 13588;     // 3 (+1 pad)
static constexpr int OFF_CAND  = 13592;     // 4 warps x 192 u64 = 1536 floats (8B aligned)
static constexpr int SMEM_FLOATS = 15128;
static constexpr int SMEM_BYTES  = SMEM_FLOATS * 4;   // 60512 B -> 3 CTAs/SM

// ---------- f32x2 packed helpers ----------
__device__ __forceinline__ u64 pk2(float a, float b) {
    u64 r; asm("mov.b64 %0,{%1,%2};" : "=l"(r) : "f"(a), "f"(b)); return r;
}
__device__ __forceinline__ void upk2(u64 v, float& a, float& b) {
    asm("mov.b64 {%0,%1},%2;" : "=f"(a), "=f"(b) : "l"(v));
}
__device__ __forceinline__ u64 f2fma(u64 a, u64 b, u64 c) {
    u64 d; asm("fma.rn.f32x2 %0,%1,%2,%3;" : "=l"(d) : "l"(a), "l"(b), "l"(c)); return d;
}
__device__ __forceinline__ u64 f2mul(u64 a, u64 b) {
    u64 d; asm("mul.rn.f32x2 %0,%1,%2;" : "=l"(d) : "l"(a), "l"(b)); return d;
}
__device__ __forceinline__ u64 f2add(u64 a, u64 b) {
    u64 d; asm("add.rn.f32x2 %0,%1,%2;" : "=l"(d) : "l"(a), "l"(b)); return d;
}

// branch-free gelu: A&S 7.1.26 erf (|abs err| <= 1.5e-7)
__device__ __forceinline__ float gelu_f(float x) {
    float z = fabsf(x) * 0.7071067811865476f;
    float t = __fdividef(1.0f, fmaf(0.3275911f, z, 1.0f));
    float p = t * fmaf(t, fmaf(t, fmaf(t, fmaf(t, 1.061405429f, -1.453152027f),
                                        1.421413741f), -0.284496736f), 0.254829592f);
    float e = __expf(-z * z);
    float er = fmaf(-p, e, 1.0f);          // erf(|x|/sqrt2)
    er = copysignf(er, x);
    return 0.5f * x * (1.0f + er);
}

__global__ void __launch_bounds__(THREADS, 3)
magno_kernel(const float* __restrict__ lat,  const float* __restrict__ rnd,
             const float* __restrict__ qry,
             const float* __restrict__ we0,  const float* __restrict__ be0,
             const float* __restrict__ we1,  const float* __restrict__ be1,
             const float* __restrict__ we2,  const float* __restrict__ be2,
             const float* __restrict__ wsw0, const float* __restrict__ bsw0,
             const float* __restrict__ wsw1, const float* __restrict__ bsw1,
             const float* __restrict__ wp0,  const float* __restrict__ bp0,
             const float* __restrict__ wp1,  const float* __restrict__ bp1,
             float* __restrict__ out)
{
    extern __shared__ float sm[];
    const int tid = threadIdx.x;

    for (int t = tid; t < NL*2;  t += THREADS) sm[OFF_COORD+t] = lat[t];
    for (int t = tid; t < 4*H;   t += THREADS) sm[OFF_WE0+t]  = we0[t];
    for (int t = tid; t < H;     t += THREADS) sm[OFF_BE0+t]  = be0[t];
    for (int t = tid; t < H*H;   t += THREADS) sm[OFF_WE1+t]  = we1[t];
    for (int t = tid; t < H;     t += THREADS) sm[OFF_BE1+t]  = be1[t];
    for (int t = tid; t < H*H;   t += THREADS) sm[OFF_WE2+t]  = we2[t];
    for (int t = tid; t < H;     t += THREADS) sm[OFF_BE2+t]  = be2[t];
    if (tid < 32)              sm[OFF_WSW0+tid]    = wsw0[tid];
    if (tid < 16)              sm[OFF_BSW0+tid]    = bsw0[tid];
    if (tid >= 32 && tid < 64) sm[OFF_WSW1+tid-32] = wsw1[tid-32];
    if (tid >= 64 && tid < 66) sm[OFF_BSW1+tid-64] = bsw1[tid-64];
    for (int t = tid; t < PH*COUT; t += THREADS) sm[OFF_WP1+t] = wp1[t];
    if (tid < COUT)            sm[OFF_BP1+tid]     = bp1[tid];
    __syncthreads();

    const int warp = tid >> 5, lane = tid & 31;
    u64* cand = (u64*)(sm + OFF_CAND) + warp * CAP;
    const float2* crd = (const float2*)(sm + OFF_COORD);

    const float R0SQ = (float)(0.055 * 0.055);
    const float R1SQ = (float)(0.11  * 0.11);
    const unsigned lt_mask = (1u << lane) - 1u;

    // per-lane constants for projection
    float bp0v[8];
#pragma unroll
    for (int jj = 0; jj < 8; jj++) bp0v[jj] = __ldg(bp0 + jj*32 + lane);

    for (int q = blockIdx.x * WARPS + warp; q < NB * NQ; q += gridDim.x * WARPS) {
        const int  bix = q >> 14;
        const float qx = qry[2*q], qy = qry[2*q+1];

        // ---- per-query scale-mixing weights ----
        float s0 = sm[OFF_BSW1+0], s1 = sm[OFF_BSW1+1];
#pragma unroll
        for (int t = 0; t < 16; t++) {
            float z = sm[OFF_BSW0+t] + qx*sm[OFF_WSW0+t] + qy*sm[OFF_WSW0+16+t];
            z = fmaxf(z, 0.0f);
            s0 = fmaf(z, sm[OFF_WSW1+2*t+0], s0);
            s1 = fmaf(z, sm[OFF_WSW1+2*t+1], s1);
        }
        float mx = fmaxf(s0, s1);
        float e0 = __expf(s0 - mx), e1 = __expf(s1 - mx);
        float inv = __fdividef(1.0f, e0 + e1);
        float sw0v = e0 * inv, sw1v = e1 * inv;

        // ---- radius-filtered candidate collection ----
        int cnt = 0;
        for (int l = lane; l < NL; l += 32) {
            float2 y = crd[l];
            float dx = qx - y.x, dy = qy - y.y;
            float d2 = __fadd_rn(__fmul_rn(dx, dx), __fmul_rn(dy, dy));
            bool pr = d2 <= R1SQ;
            unsigned m = __ballot_sync(FULLMASK, pr);
            if (pr) {
                int pos = cnt + __popc(m & lt_mask);
                if (pos < CAP)
                    cand[pos] = ((u64)__float_as_uint(d2) << 32) | (unsigned)l;
            }
            cnt += __popc(m);
        }
        if (cnt > CAP) cnt = CAP;
        __syncwarp();

        // ---- exact K=32 smallest selection ----
        u64 mykey = 0x7f7fffff00000000ull;
        int nsel;
        if (cnt <= KCAP) {
            nsel = cnt;
            if (lane < cnt) mykey = cand[lane];
        } else {
            nsel = KCAP;
            for (int r = 0; r < KCAP; r++) {
                u64 best = ~0ull;
                for (int p = lane; p < cnt; p += 32) {
                    u64 v = cand[p];
                    if (v < best) best = v;
                }
#pragma unroll
                for (int off = 16; off > 0; off >>= 1) {
                    u64 o = __shfl_xor_sync(FULLMASK, best, off);
                    if (o < best) best = o;
                }
                if (lane == r) mykey = best;
                for (int p = lane; p < cnt; p += 32)
                    if (cand[p] == best) cand[p] = ~0ull;
                __syncwarp();
            }
        }
        float seld2  = __uint_as_float((unsigned)(mykey >> 32));
        int   selidx = (int)(mykey & 0xffffffffu);
        if (lane >= nsel) { seld2 = 3.4e38f; selidx = 0; }

        bool v0 = (lane < nsel) && (seld2 <= R0SQ);
        int  c0 = __popc(__ballot_sync(FULLMASK, v0));
        float coeff = 0.0f;
        if (v0)          coeff += sw0v / (float)(c0   > 1 ? c0   : 1);
        if (lane < nsel) coeff += sw1v / (float)(nsel > 1 ? nsel : 1);

        // ---- layer 0: [yx,yy,qx,qy] @ W0 + b0 -> gelu -> h[64] (registers) ----
        float h[64];
        {
            float2 yc = crd[selidx];
            u64 yx2 = pk2(yc.x, yc.x), yy2 = pk2(yc.y, yc.y);
            u64 qx2 = pk2(qx, qx),     qy2 = pk2(qy, qy);
            const u64* w0r0 = (const u64*)(sm + OFF_WE0);
            const u64* w0r1 = (const u64*)(sm + OFF_WE0 + 64);
            const u64* w0r2 = (const u64*)(sm + OFF_WE0 + 128);
            const u64* w0r3 = (const u64*)(sm + OFF_WE0 + 192);
            const u64* b0p  = (const u64*)(sm + OFF_BE0);
#pragma unroll
            for (int jp = 0; jp < 32; jp++) {
                u64 t = b0p[jp];
                t = f2fma(yx2, w0r0[jp], t);
                t = f2fma(yy2, w0r1[jp], t);
                t = f2fma(qx2, w0r2[jp], t);
                t = f2fma(qy2, w0r3[jp], t);
                float a, b; upk2(t, a, b);
                h[2*jp]   = gelu_f(a);
                h[2*jp+1] = gelu_f(b);
            }
        }

        // ---- layer 1: h @ W1 + b1 -> gelu (f32x2 packed output channels) ----
        u64 acc[32];
        {
            const u64* b1p = (const u64*)(sm + OFF_BE1);
#pragma unroll
            for (int p = 0; p < 32; p++) acc[p] = b1p[p];
            const ulonglong2* w1 = (const ulonglong2*)(sm + OFF_WE1);
#pragma unroll
            for (int i = 0; i < 64; i++) {
                u64 hh = pk2(h[i], h[i]);
                const ulonglong2* row = w1 + i * 16;
#pragma unroll
                for (int j2 = 0; j2 < 16; j2++) {
                    ulonglong2 w = row[j2];
                    acc[2*j2]   = f2fma(hh, w.x, acc[2*j2]);
                    acc[2*j2+1] = f2fma(hh, w.y, acc[2*j2+1]);
                }
            }
#pragma unroll
            for (int p = 0; p < 32; p++) {
                float a, b; upk2(acc[p], a, b);
                h[2*p]   = gelu_f(a);
                h[2*p+1] = gelu_f(b);
            }
        }

        // ---- layer 2: h @ W2 + b2 (f32x2) ----
        {
            const u64* b2p = (const u64*)(sm + OFF_BE2);
#pragma unroll
            for (int p = 0; p < 32; p++) acc[p] = b2p[p];
            const ulonglong2* w2 = (const ulonglong2*)(sm + OFF_WE2);
#pragma unroll
            for (int i = 0; i < 64; i++) {
                u64 hh = pk2(h[i], h[i]);
                const ulonglong2* row = w2 + i * 16;
#pragma unroll
                for (int j2 = 0; j2 < 16; j2++) {
                    ulonglong2 w = row[j2];
                    acc[2*j2]   = f2fma(hh, w.x, acc[2*j2]);
                    acc[2*j2+1] = f2fma(hh, w.y, acc[2*j2+1]);
                }
            }
        }

        // ---- rep = k(x,y) * f(y) * coeff ; warp-sum over neighbors ----
        {
            u64 cc = pk2(coeff, coeff);
            const float4* frow = (const float4*)(rnd + (size_t)(bix * NL + selidx) * H);
#pragma unroll
            for (int j4 = 0; j4 < 16; j4++) {
                float4 f4 = __ldg(frow + j4);
                acc[2*j4]   = f2mul(acc[2*j4],   f2mul(pk2(f4.x, f4.y), cc));
                acc[2*j4+1] = f2mul(acc[2*j4+1], f2mul(pk2(f4.z, f4.w), cc));
            }
#pragma unroll
            for (int p = 0; p < 32; p++) {
                u64 v = acc[p];
#pragma unroll
                for (int off = 16; off > 0; off >>= 1)
                    v = f2add(v, __shfl_xor_sync(FULLMASK, v, off));
                acc[p] = v;   // every lane now holds the full sum
            }
        }

        // ---- projection MLP: 64 -> 256 (gelu) -> 3 ; lane = PH slice ----
        float hp[8];
#pragma unroll
        for (int jj = 0; jj < 8; jj++) hp[jj] = bp0v[jj];
#pragma unroll
        for (int p = 0; p < 32; p++) {
            float d0, d1; upk2(acc[p], d0, d1);
            const float* w0r = wp0 + (2*p) * PH + lane;
            const float* w1r = wp0 + (2*p+1) * PH + lane;
#pragma unroll
            for (int jj = 0; jj < 8; jj++)
                hp[jj] = fmaf(d0, __ldg(w0r + jj*32), hp[jj]);
#pragma unroll
            for (int jj = 0; jj < 8; jj++)
                hp[jj] = fmaf(d1, __ldg(w1r + jj*32), hp[jj]);
        }
#pragma unroll
        for (int jj = 0; jj < 8; jj++) hp[jj] = gelu_f(hp[jj]);

        float o0 = 0.f, o1 = 0.f, o2 = 0.f;
#pragma unroll
        for (int jj = 0; jj < 8; jj++) {
            int row = jj*32 + lane;
            float hv = hp[jj];
            o0 = fmaf(hv, sm[OFF_WP1 + row*3 + 0], o0);
            o1 = fmaf(hv, sm[OFF_WP1 + row*3 + 1], o1);
            o2 = fmaf(hv, sm[OFF_WP1 + row*3 + 2], o2);
        }
#pragma unroll
        for (int off = 16; off > 0; off >>= 1) {
            o0 += __shfl_xor_sync(FULLMASK, o0, off);
            o1 += __shfl_xor_sync(FULLMASK, o1, off);
            o2 += __shfl_xor_sync(FULLMASK, o2, off);
        }
        if (lane == 0) {
            out[q*COUT + 0] = o0 + sm[OFF_BP1 + 0];
            out[q*COUT + 1] = o1 + sm[OFF_BP1 + 1];
            out[q*COUT + 2] = o2 + sm[OFF_BP1 + 2];
        }
        __syncwarp();
    }
}

extern "C" void kernel_launch(void* const* d_in, const int* in_sizes, int n_in,
                              void* d_out, int out_size) {
    const float* lat  = (const float*)d_in[0];
    const float* rnd  = (const float*)d_in[1];
    const float* qry  = (const float*)d_in[2];
    const float* we0  = (const float*)d_in[3];
    const float* be0  = (const float*)d_in[4];
    const float* we1  = (const float*)d_in[5];
    const float* be1  = (const float*)d_in[6];
    const float* we2  = (const float*)d_in[7];
    const float* be2  = (const float*)d_in[8];
    const float* wsw0 = (const float*)d_in[9];
    const float* bsw0 = (const float*)d_in[10];
    const float* wsw1 = (const float*)d_in[11];
    const float* bsw1 = (const float*)d_in[12];
    const float* wp0  = (const float*)d_in[13];
    const float* bp0  = (const float*)d_in[14];
    const float* wp1  = (const float*)d_in[15];
    const float* bp1  = (const float*)d_in[16];
    float* out = (float*)d_out;

    cudaFuncSetAttribute(magno_kernel, cudaFuncAttributeMaxDynamicSharedMemorySize, SMEM_BYTES);
    magno_kernel<<<NBLOCK, THREADS, SMEM_BYTES>>>(
        lat, rnd, qry, we0, be0, we1, be1, we2, be2,
        wsw0, bsw0, wsw1, bsw1, wp0, bp0, wp1, bp1, out);
}

// round 3
// speedup vs baseline: 1.0664x; 1.0664x over previous
#include <cuda_runtime.h>
#include <math.h>

#define FULLMASK 0xffffffffu
typedef unsigned long long u64;

static constexpr int NL     = 2048;
static constexpr int NQ     = 16384;
static constexpr int NB     = 2;
static constexpr int H      = 64;
static constexpr int PH     = 256;
static constexpr int COUT   = 3;
static constexpr int KCAP   = 32;
static constexpr int CAP    = 192;
static constexpr int THREADS= 128;
static constexpr int WARPS  = 4;
static constexpr int NBLOCK = 444;   // 148 SMs x 3 CTAs

// W1 + b1 live in constant memory (separate uniform-const load port)
__constant__ float4 cW1[H * H / 4];   // [64][16] float4, row-major
__constant__ float  cB1[H];

// ---- dynamic shared memory layout (float offsets) ----
static constexpr int OFF_COORD = 0;         // 4096
static constexpr int OFF_WE0   = 4096;      // 256   [4][64]
static constexpr int OFF_BE0   = 4352;      // 64
static constexpr int OFF_WE2   = 4416;      // 4096  (16B aligned)
static constexpr int OFF_BE2   = 8512;      // 64
static constexpr int OFF_WSW0  = 8576;      // 32
static constexpr int OFF_BSW0  = 8608;      // 16
static constexpr int OFF_WSW1  = 8624;      // 32
static constexpr int OFF_BSW1  = 8656;      // 2 (+2 pad)
static constexpr int OFF_WP1T  = 8660;      // 768 = [3][256] transposed (16B aligned)
static constexpr int OFF_BP1   = 9428;      // 3 (+1 pad)
static constexpr int OFF_CAND  = 9432;      // 4 warps x 192 u64 (8B aligned)
static constexpr int SMEM_FLOATS = 10968;
static constexpr int SMEM_BYTES  = SMEM_FLOATS * 4;   // 43872 B

// ---------- f32x2 packed helpers ----------
__device__ __forceinline__ u64 pk2(float a, float b) {
    u64 r; asm("mov.b64 %0,{%1,%2};" : "=l"(r) : "f"(a), "f"(b)); return r;
}
__device__ __forceinline__ void upk2(u64 v, float& a, float& b) {
    asm("mov.b64 {%0,%1},%2;" : "=f"(a), "=f"(b) : "l"(v));
}
__device__ __forceinline__ u64 f2fma(u64 a, u64 b, u64 c) {
    u64 d; asm("fma.rn.f32x2 %0,%1,%2,%3;" : "=l"(d) : "l"(a), "l"(b), "l"(c)); return d;
}
__device__ __forceinline__ u64 f2mul(u64 a, u64 b) {
    u64 d; asm("mul.rn.f32x2 %0,%1,%2;" : "=l"(d) : "l"(a), "l"(b)); return d;
}
__device__ __forceinline__ u64 f2add(u64 a, u64 b) {
    u64 d; asm("add.rn.f32x2 %0,%1,%2;" : "=l"(d) : "l"(a), "l"(b)); return d;
}

// branch-free gelu: A&S 7.1.26 erf (|abs err| <= 1.5e-7)
__device__ __forceinline__ float gelu_f(float x) {
    float z = fabsf(x) * 0.7071067811865476f;
    float t = __fdividef(1.0f, fmaf(0.3275911f, z, 1.0f));
    float p = t * fmaf(t, fmaf(t, fmaf(t, fmaf(t, 1.061405429f, -1.453152027f),
                                        1.421413741f), -0.284496736f), 0.254829592f);
    float e = __expf(-z * z);
    float er = fmaf(-p, e, 1.0f);
    er = copysignf(er, x);
    return 0.5f * x * (1.0f + er);
}

__device__ __forceinline__ float key_d2(u64 k) {
    return __uint_as_float((unsigned)(k >> 32));   // NaN when k == ~0ull
}
__device__ __forceinline__ void ce(u64& a, u64& b) {  // compare-exchange
    u64 lo = a < b ? a : b;
    u64 hi = a < b ? b : a;
    a = lo; b = hi;
}

__global__ void __launch_bounds__(THREADS, 3)
magno_kernel(const float* __restrict__ lat,  const float* __restrict__ rnd,
             const float* __restrict__ qry,
             const float* __restrict__ we0,  const float* __restrict__ be0,
             const float* __restrict__ we2,  const float* __restrict__ be2,
             const float* __restrict__ wsw0, const float* __restrict__ bsw0,
             const float* __restrict__ wsw1, const float* __restrict__ bsw1,
             const float* __restrict__ wp0,  const float* __restrict__ bp0,
             const float* __restrict__ wp1,  const float* __restrict__ bp1,
             float* __restrict__ out)
{
    extern __shared__ float sm[];
    const int tid = threadIdx.x;

    for (int t = tid; t < NL*2;  t += THREADS) sm[OFF_COORD+t] = lat[t];
    for (int t = tid; t < 4*H;   t += THREADS) sm[OFF_WE0+t]  = we0[t];
    for (int t = tid; t < H;     t += THREADS) sm[OFF_BE0+t]  = be0[t];
    for (int t = tid; t < H*H;   t += THREADS) sm[OFF_WE2+t]  = we2[t];
    for (int t = tid; t < H;     t += THREADS) sm[OFF_BE2+t]  = be2[t];
    if (tid < 32)              sm[OFF_WSW0+tid]    = wsw0[tid];
    if (tid < 16)              sm[OFF_BSW0+tid]    = bsw0[tid];
    if (tid >= 32 && tid < 64) sm[OFF_WSW1+tid-32] = wsw1[tid-32];
    if (tid >= 64 && tid < 66) sm[OFF_BSW1+tid-64] = bsw1[tid-64];
    // wp1 transposed: [3][256]
    for (int t = tid; t < COUT*PH; t += THREADS) {
        int c = t >> 8, row = t & 255;
        sm[OFF_WP1T + c*PH + row] = wp1[row*COUT + c];
    }
    if (tid < COUT)            sm[OFF_BP1+tid]     = bp1[tid];
    __syncthreads();

    const int warp = tid >> 5, lane = tid & 31;
    u64* cand = (u64*)(sm + OFF_CAND) + warp * CAP;
    const float2* crd = (const float2*)(sm + OFF_COORD);

    const float R0SQ = (float)(0.055 * 0.055);
    const float R1SQ = (float)(0.11  * 0.11);
    const unsigned lt_mask = (1u << lane) - 1u;

    // per-lane projection constants (contiguous columns 8*lane .. 8*lane+7)
    u64 bp0p[4];
    {
        const ulonglong2* bp = (const ulonglong2*)(bp0 + 8*lane);
        ulonglong2 b0 = bp[0], b1 = bp[1];
        bp0p[0] = b0.x; bp0p[1] = b0.y; bp0p[2] = b1.x; bp0p[3] = b1.y;
    }

    for (int q = blockIdx.x * WARPS + warp; q < NB * NQ; q += gridDim.x * WARPS) {
        const int  bix = q >> 14;
        const float qx = qry[2*q], qy = qry[2*q+1];

        // ---- per-query scale-mixing weights ----
        float s0 = sm[OFF_BSW1+0], s1 = sm[OFF_BSW1+1];
#pragma unroll
        for (int t = 0; t < 16; t++) {
            float z = sm[OFF_BSW0+t] + qx*sm[OFF_WSW0+t] + qy*sm[OFF_WSW0+16+t];
            z = fmaxf(z, 0.0f);
            s0 = fmaf(z, sm[OFF_WSW1+2*t+0], s0);
            s1 = fmaf(z, sm[OFF_WSW1+2*t+1], s1);
        }
        float mx = fmaxf(s0, s1);
        float e0 = __expf(s0 - mx), e1 = __expf(s1 - mx);
        float inv = __fdividef(1.0f, e0 + e1);
        float sw0v = e0 * inv, sw1v = e1 * inv;

        // ---- radius-filtered candidate collection ----
        int cnt = 0;
        for (int l = lane; l < NL; l += 32) {
            float2 y = crd[l];
            float dx = qx - y.x, dy = qy - y.y;
            float d2 = __fadd_rn(__fmul_rn(dx, dx), __fmul_rn(dy, dy));
            bool pr = d2 <= R1SQ;
            unsigned m = __ballot_sync(FULLMASK, pr);
            if (pr) {
                int pos = cnt + __popc(m & lt_mask);
                if (pos < CAP)
                    cand[pos] = ((u64)__float_as_uint(d2) << 32) | (unsigned)l;
            }
            cnt += __popc(m);
        }
        if (cnt > CAP) cnt = CAP;
        __syncwarp();

        // ---- exact K=32 smallest selection (register-resident heads) ----
        u64 mykey = 0x7f7fffff00000000ull;
        int nsel;
        if (cnt <= KCAP) {
            nsel = cnt;
            if (lane < cnt) mykey = cand[lane];
        } else {
            nsel = KCAP;
            u64 c0, c1, c2, c3, c4, c5;
            {
                int p;
                p = lane;        c0 = (p < cnt) ? cand[p] : ~0ull;
                p = lane + 32;   c1 = (p < cnt) ? cand[p] : ~0ull;
                p = lane + 64;   c2 = (p < cnt) ? cand[p] : ~0ull;
                p = lane + 96;   c3 = (p < cnt) ? cand[p] : ~0ull;
                p = lane + 128;  c4 = (p < cnt) ? cand[p] : ~0ull;
                p = lane + 160;  c5 = (p < cnt) ? cand[p] : ~0ull;
            }
            // sort 6 (Bose-Nelson network, 12 CE)
            ce(c0,c1); ce(c2,c3); ce(c4,c5);
            ce(c0,c2); ce(c3,c5); ce(c1,c4);
            ce(c0,c1); ce(c2,c3); ce(c4,c5);
            ce(c1,c2); ce(c3,c4); ce(c2,c3);

            float hd = key_d2(c0);
#pragma unroll 1
            for (int r = 0; r < KCAP; r++) {
                float m = hd;
#pragma unroll
                for (int off = 16; off > 0; off >>= 1)
                    m = fminf(m, __shfl_xor_sync(FULLMASK, m, off));
                unsigned tied = __ballot_sync(FULLMASK, hd == m);
                int src;
                if ((tied & (tied - 1u)) == 0u) {
                    src = __ffs(tied) - 1;
                } else {
                    // rare exact-d2 tie: break by smaller latent index
                    unsigned mi = (tied >> lane & 1u) ? (unsigned)c0 : 0xffffffffu;
#pragma unroll
                    for (int off = 16; off > 0; off >>= 1)
                        mi = min(mi, __shfl_xor_sync(FULLMASK, mi, off));
                    unsigned om = __ballot_sync(FULLMASK,
                        (tied >> lane & 1u) && ((unsigned)c0 == mi));
                    src = __ffs(om) - 1;
                }
                u64 win = __shfl_sync(FULLMASK, c0, src);
                if (lane == r) mykey = win;
                if (lane == src) {
                    c0 = c1; c1 = c2; c2 = c3; c3 = c4; c4 = c5; c5 = ~0ull;
                    hd = key_d2(c0);
                }
            }
        }
        float seld2  = __uint_as_float((unsigned)(mykey >> 32));
        int   selidx = (int)(mykey & 0xffffffffu);
        if (lane >= nsel) { seld2 = 3.4e38f; selidx = 0; }

        bool v0 = (lane < nsel) && (seld2 <= R0SQ);
        int  c0cnt = __popc(__ballot_sync(FULLMASK, v0));
        float coeff = 0.0f;
        if (v0)          coeff += sw0v / (float)(c0cnt > 1 ? c0cnt : 1);
        if (lane < nsel) coeff += sw1v / (float)(nsel  > 1 ? nsel  : 1);

        // ---- layer 0: [yx,yy,qx,qy] @ W0 + b0 -> gelu -> h[64] ----
        float h[64];
        {
            float2 yc = crd[selidx];
            u64 yx2 = pk2(yc.x, yc.x), yy2 = pk2(yc.y, yc.y);
            u64 qx2 = pk2(qx, qx),     qy2 = pk2(qy, qy);
            const u64* w0r0 = (const u64*)(sm + OFF_WE0);
            const u64* w0r1 = (const u64*)(sm + OFF_WE0 + 64);
            const u64* w0r2 = (const u64*)(sm + OFF_WE0 + 128);
            const u64* w0r3 = (const u64*)(sm + OFF_WE0 + 192);
            const u64* b0p  = (const u64*)(sm + OFF_BE0);
#pragma unroll
            for (int jp = 0; jp < 32; jp++) {
                u64 t = b0p[jp];
                t = f2fma(yx2, w0r0[jp], t);
                t = f2fma(yy2, w0r1[jp], t);
                t = f2fma(qx2, w0r2[jp], t);
                t = f2fma(qy2, w0r3[jp], t);
                float a, b; upk2(t, a, b);
                h[2*jp]   = gelu_f(a);
                h[2*jp+1] = gelu_f(b);
            }
        }

        // ---- layer 1: h @ W1 + b1 -> gelu  (W1 in constant memory, scalar FFMA) ----
        {
            float a1[64];
#pragma unroll
            for (int j = 0; j < 64; j++) a1[j] = cB1[j];
#pragma unroll
            for (int i = 0; i < 64; i++) {
                float hv = h[i];
#pragma unroll
                for (int j4 = 0; j4 < 16; j4++) {
                    float4 w = cW1[i*16 + j4];
                    a1[4*j4+0] = fmaf(hv, w.x, a1[4*j4+0]);
                    a1[4*j4+1] = fmaf(hv, w.y, a1[4*j4+1]);
                    a1[4*j4+2] = fmaf(hv, w.z, a1[4*j4+2]);
                    a1[4*j4+3] = fmaf(hv, w.w, a1[4*j4+3]);
                }
            }
#pragma unroll
            for (int j = 0; j < 64; j++) h[j] = gelu_f(a1[j]);
        }

        // ---- layer 2: h @ W2 + b2 (SMEM, f32x2) ----
        u64 acc[32];
        {
            const u64* b2p = (const u64*)(sm + OFF_BE2);
#pragma unroll
            for (int p = 0; p < 32; p++) acc[p] = b2p[p];
            const ulonglong2* w2 = (const ulonglong2*)(sm + OFF_WE2);
#pragma unroll
            for (int i = 0; i < 64; i++) {
                u64 hh = pk2(h[i], h[i]);
                const ulonglong2* row = w2 + i * 16;
#pragma unroll
                for (int j2 = 0; j2 < 16; j2++) {
                    ulonglong2 w = row[j2];
                    acc[2*j2]   = f2fma(hh, w.x, acc[2*j2]);
                    acc[2*j2+1] = f2fma(hh, w.y, acc[2*j2+1]);
                }
            }
        }

        // ---- rep = k(x,y) * f(y) * coeff ; warp-sum over neighbors ----
        {
            u64 cc = pk2(coeff, coeff);
            const float4* frow = (const float4*)(rnd + (size_t)(bix * NL + selidx) * H);
#pragma unroll
            for (int j4 = 0; j4 < 16; j4++) {
                float4 f4 = __ldg(frow + j4);
                acc[2*j4]   = f2mul(acc[2*j4],   f2mul(pk2(f4.x, f4.y), cc));
                acc[2*j4+1] = f2mul(acc[2*j4+1], f2mul(pk2(f4.z, f4.w), cc));
            }
#pragma unroll
            for (int p = 0; p < 32; p++) {
                u64 v = acc[p];
#pragma unroll
                for (int off = 16; off > 0; off >>= 1)
                    v = f2add(v, __shfl_xor_sync(FULLMASK, v, off));
                acc[p] = v;
            }
        }

        // ---- projection MLP: 64 -> 256 (gelu) -> 3 ; lane owns cols 8l..8l+7 ----
        u64 hp2[4];
#pragma unroll
        for (int jj = 0; jj < 4; jj++) hp2[jj] = bp0p[jj];
#pragma unroll
        for (int p = 0; p < 32; p++) {
            float d0, d1; upk2(acc[p], d0, d1);
            u64 dd0 = pk2(d0, d0), dd1 = pk2(d1, d1);
            const ulonglong2* r0 = (const ulonglong2*)(wp0 + (2*p)*PH   + 8*lane);
            const ulonglong2* r1 = (const ulonglong2*)(wp0 + (2*p+1)*PH + 8*lane);
            ulonglong2 wa = r0[0], wb = r0[1];
            hp2[0] = f2fma(dd0, wa.x, hp2[0]);
            hp2[1] = f2fma(dd0, wa.y, hp2[1]);
            hp2[2] = f2fma(dd0, wb.x, hp2[2]);
            hp2[3] = f2fma(dd0, wb.y, hp2[3]);
            ulonglong2 wc = r1[0], wd = r1[1];
            hp2[0] = f2fma(dd1, wc.x, hp2[0]);
            hp2[1] = f2fma(dd1, wc.y, hp2[1]);
            hp2[2] = f2fma(dd1, wd.x, hp2[2]);
            hp2[3] = f2fma(dd1, wd.y, hp2[3]);
        }
        float hpf[8];
#pragma unroll
        for (int jj = 0; jj < 4; jj++) {
            float a, b; upk2(hp2[jj], a, b);
            hpf[2*jj]   = gelu_f(a);
            hpf[2*jj+1] = gelu_f(b);
        }

        float o0 = 0.f, o1 = 0.f, o2 = 0.f;
#pragma unroll
        for (int c = 0; c < COUT; c++) {
            const float4* w = (const float4*)(sm + OFF_WP1T + c*PH + 8*lane);
            float4 w0v = w[0], w1v = w[1];
            float oc;
            oc = hpf[0]*w0v.x;
            oc = fmaf(hpf[1], w0v.y, oc);
            oc = fmaf(hpf[2], w0v.z, oc);
            oc = fmaf(hpf[3], w0v.w, oc);
            oc = fmaf(hpf[4], w1v.x, oc);
            oc = fmaf(hpf[5], w1v.y, oc);
            oc = fmaf(hpf[6], w1v.z, oc);
            oc = fmaf(hpf[7], w1v.w, oc);
            if (c == 0) o0 = oc; else if (c == 1) o1 = oc; else o2 = oc;
        }
#pragma unroll
        for (int off = 16; off > 0; off >>= 1) {
            o0 += __shfl_xor_sync(FULLMASK, o0, off);
            o1 += __shfl_xor_sync(FULLMASK, o1, off);
            o2 += __shfl_xor_sync(FULLMASK, o2, off);
        }
        if (lane == 0) {
            out[q*COUT + 0] = o0 + sm[OFF_BP1 + 0];
            out[q*COUT + 1] = o1 + sm[OFF_BP1 + 1];
            out[q*COUT + 2] = o2 + sm[OFF_BP1 + 2];
        }
        __syncwarp();
    }
}

extern "C" void kernel_launch(void* const* d_in, const int* in_sizes, int n_in,
                              void* d_out, int out_size) {
    const float* lat  = (const float*)d_in[0];
    const float* rnd  = (const float*)d_in[1];
    const float* qry  = (const float*)d_in[2];
    const float* we0  = (const float*)d_in[3];
    const float* be0  = (const float*)d_in[4];
    const float* we1  = (const float*)d_in[5];
    const float* be1  = (const float*)d_in[6];
    const float* we2  = (const float*)d_in[7];
    const float* be2  = (const float*)d_in[8];
    const float* wsw0 = (const float*)d_in[9];
    const float* bsw0 = (const float*)d_in[10];
    const float* wsw1 = (const float*)d_in[11];
    const float* bsw1 = (const float*)d_in[12];
    const float* wp0  = (const float*)d_in[13];
    const float* bp0  = (const float*)d_in[14];
    const float* wp1  = (const float*)d_in[15];
    const float* bp1  = (const float*)d_in[16];
    float* out = (float*)d_out;

    cudaMemcpyToSymbolAsync(cW1, we1, H*H*sizeof(float), 0,
                            cudaMemcpyDeviceToDevice, 0);
    cudaMemcpyToSymbolAsync(cB1, be1, H*sizeof(float), 0,
                            cudaMemcpyDeviceToDevice, 0);

    cudaFuncSetAttribute(magno_kernel, cudaFuncAttributeMaxDynamicSharedMemorySize, SMEM_BYTES);
    magno_kernel<<<NBLOCK, THREADS, SMEM_BYTES>>>(
        lat, rnd, qry, we0, be0, we2, be2,
        wsw0, bsw0, wsw1, bsw1, wp0, bp0, wp1, bp1, out);
}

// round 5
// speedup vs baseline: 1.5491x; 1.4526x over previous
#include <cuda_runtime.h>
#include <math.h>

#define FULLMASK 0xffffffffu
typedef unsigned long long u64;

static constexpr int NL     = 2048;
static constexpr int NQ     = 16384;
static constexpr int NB     = 2;
static constexpr int H      = 64;
static constexpr int PH     = 256;
static constexpr int COUT   = 3;
static constexpr int KCAP   = 32;
static constexpr int CAP    = 160;
static constexpr int THREADS= 128;
static constexpr int WARPS  = 4;
static constexpr int NBLOCK = 592;   // 148 SMs x 4 CTAs

// ---- dynamic shared memory layout (float offsets) ----
static constexpr int OFF_W1    = 0;         // 4096  [64][64], j contiguous
static constexpr int OFF_W2    = 4096;      // 4096
static constexpr int OFF_WE0   = 8192;      // 256   [4][64]
static constexpr int OFF_BE0   = 8448;      // 64
static constexpr int OFF_BE1   = 8512;      // 64
static constexpr int OFF_BE2   = 8576;      // 64
static constexpr int OFF_WSW0  = 8640;      // 32
static constexpr int OFF_BSW0  = 8672;      // 16
static constexpr int OFF_WSW1  = 8688;      // 32
static constexpr int OFF_BSW1  = 8720;      // 2 (+2 pad)
static constexpr int OFF_WP1T  = 8724;      // 768 = [3][256] transposed (16B aligned)
static constexpr int OFF_BP1   = 9492;      // 3 (+1 pad)
static constexpr int OFF_CAND  = 9496;      // 4 warps x 160 u64 = 1280 floats
static constexpr int SMEM_FLOATS = 10776;
static constexpr int SMEM_BYTES  = SMEM_FLOATS * 4;   // 43104 B -> 4 CTAs/SM ok

// ---------- f32x2 packed helpers ----------
__device__ __forceinline__ u64 pk2(float a, float b) {
    u64 r; asm("mov.b64 %0,{%1,%2};" : "=l"(r) : "f"(a), "f"(b)); return r;
}
__device__ __forceinline__ void upk2(u64 v, float& a, float& b) {
    asm("mov.b64 {%0,%1},%2;" : "=f"(a), "=f"(b) : "l"(v));
}
__device__ __forceinline__ u64 f2fma(u64 a, u64 b, u64 c) {
    u64 d; asm("fma.rn.f32x2 %0,%1,%2,%3;" : "=l"(d) : "l"(a), "l"(b), "l"(c)); return d;
}
__device__ __forceinline__ u64 f2mul(u64 a, u64 b) {
    u64 d; asm("mul.rn.f32x2 %0,%1,%2;" : "=l"(d) : "l"(a), "l"(b)); return d;
}
__device__ __forceinline__ u64 f2add(u64 a, u64 b) {
    u64 d; asm("add.rn.f32x2 %0,%1,%2;" : "=l"(d) : "l"(a), "l"(b)); return d;
}
// packed butterfly reduction: both f32 lanes of the u64 summed across warp
__device__ __forceinline__ u64 wsum2(u64 v) {
#pragma unroll
    for (int off = 16; off > 0; off >>= 1)
        v = f2add(v, __shfl_xor_sync(FULLMASK, v, off));
    return v;
}
__device__ __forceinline__ unsigned redux_min_u32(unsigned v) {
    unsigned r; asm("redux.sync.min.u32 %0, %1, 0xffffffff;" : "=r"(r) : "r"(v)); return r;
}

// branch-free gelu: A&S 7.1.26 erf (|abs err| <= 1.5e-7)
__device__ __forceinline__ float gelu_f(float x) {
    float z = fabsf(x) * 0.7071067811865476f;
    float t = __fdividef(1.0f, fmaf(0.3275911f, z, 1.0f));
    float p = t * fmaf(t, fmaf(t, fmaf(t, fmaf(t, 1.061405429f, -1.453152027f),
                                        1.421413741f), -0.284496736f), 0.254829592f);
    float e = __expf(-z * z);
    float er = fmaf(-p, e, 1.0f);
    er = copysignf(er, x);
    return 0.5f * x * (1.0f + er);
}

__device__ __forceinline__ void ce(u64& a, u64& b) {  // compare-exchange
    u64 lo = a < b ? a : b;
    u64 hi = a < b ? b : a;
    a = lo; b = hi;
}

__global__ void __launch_bounds__(THREADS, 4)
magno_kernel(const float* __restrict__ lat,  const float* __restrict__ rnd,
             const float* __restrict__ qry,
             const float* __restrict__ we0,  const float* __restrict__ be0,
             const float* __restrict__ we1,  const float* __restrict__ be1,
             const float* __restrict__ we2,  const float* __restrict__ be2,
             const float* __restrict__ wsw0, const float* __restrict__ bsw0,
             const float* __restrict__ wsw1, const float* __restrict__ bsw1,
             const float* __restrict__ wp0,  const float* __restrict__ bp0,
             const float* __restrict__ wp1,  const float* __restrict__ bp1,
             float* __restrict__ out)
{
    extern __shared__ float sm[];
    const int tid = threadIdx.x;

    for (int t = tid; t < H*H;  t += THREADS) sm[OFF_W1+t]  = we1[t];
    for (int t = tid; t < H*H;  t += THREADS) sm[OFF_W2+t]  = we2[t];
    for (int t = tid; t < 4*H;  t += THREADS) sm[OFF_WE0+t] = we0[t];
    for (int t = tid; t < H;    t += THREADS) sm[OFF_BE0+t] = be0[t];
    for (int t = tid; t < H;    t += THREADS) sm[OFF_BE1+t] = be1[t];
    for (int t = tid; t < H;    t += THREADS) sm[OFF_BE2+t] = be2[t];
    if (tid < 32)              sm[OFF_WSW0+tid]    = wsw0[tid];
    if (tid < 16)              sm[OFF_BSW0+tid]    = bsw0[tid];
    if (tid >= 32 && tid < 64) sm[OFF_WSW1+tid-32] = wsw1[tid-32];
    if (tid >= 64 && tid < 66) sm[OFF_BSW1+tid-64] = bsw1[tid-64];
    for (int t = tid; t < COUT*PH; t += THREADS) {
        int c = t >> 8, row = t & 255;
        sm[OFF_WP1T + c*PH + row] = wp1[row*COUT + c];
    }
    if (tid < COUT)            sm[OFF_BP1+tid]     = bp1[tid];
    __syncthreads();

    const int warp = tid >> 5, lane = tid & 31;
    u64* cand = (u64*)(sm + OFF_CAND) + warp * CAP;
    const float2* latf2 = (const float2*)lat;

    const float R0SQ = (float)(0.055 * 0.055);
    const float R1SQ = (float)(0.11  * 0.11);
    const unsigned lt_mask = (1u << lane) - 1u;

    // per-lane projection constants (columns 8*lane .. 8*lane+7)
    u64 bp0p[4];
    {
        const ulonglong2* bp = (const ulonglong2*)(bp0 + 8*lane);
        ulonglong2 b0 = bp[0], b1 = bp[1];
        bp0p[0] = b0.x; bp0p[1] = b0.y; bp0p[2] = b1.x; bp0p[3] = b1.y;
    }

    for (int q = blockIdx.x * WARPS + warp; q < NB * NQ; q += gridDim.x * WARPS) {
        const int  bix = q >> 14;
        const float qx = qry[2*q], qy = qry[2*q+1];

        // ---- per-query scale-mixing weights ----
        float s0 = sm[OFF_BSW1+0], s1 = sm[OFF_BSW1+1];
#pragma unroll
        for (int t = 0; t < 16; t++) {
            float z = sm[OFF_BSW0+t] + qx*sm[OFF_WSW0+t] + qy*sm[OFF_WSW0+16+t];
            z = fmaxf(z, 0.0f);
            s0 = fmaf(z, sm[OFF_WSW1+2*t+0], s0);
            s1 = fmaf(z, sm[OFF_WSW1+2*t+1], s1);
        }
        float mx = fmaxf(s0, s1);
        float e0 = __expf(s0 - mx), e1 = __expf(s1 - mx);
        float inv = __fdividef(1.0f, e0 + e1);
        float sw0v = e0 * inv, sw1v = e1 * inv;

        // ---- radius-filtered candidate collection (coords via L1) ----
        int cnt = 0;
        for (int l = lane; l < NL; l += 32) {
            float2 y = __ldg(latf2 + l);
            float dx = qx - y.x, dy = qy - y.y;
            float d2 = __fadd_rn(__fmul_rn(dx, dx), __fmul_rn(dy, dy));
            bool pr = d2 <= R1SQ;
            unsigned m = __ballot_sync(FULLMASK, pr);
            if (pr) {
                int pos = cnt + __popc(m & lt_mask);
                if (pos < CAP)
                    cand[pos] = ((u64)__float_as_uint(d2) << 32) | (unsigned)l;
            }
            cnt += __popc(m);
        }
        if (cnt > CAP) cnt = CAP;
        __syncwarp();

        // ---- exact K=32 smallest selection ----
        u64 mykey = 0x7f7fffff00000000ull;
        int nsel;
        if (cnt <= KCAP) {
            nsel = cnt;
            if (lane < cnt) mykey = cand[lane];
        } else {
            nsel = KCAP;
            u64 c0, c1, c2, c3, c4, c5;
            c0 = (lane       < cnt) ? cand[lane      ] : ~0ull;
            c1 = (lane + 32  < cnt) ? cand[lane + 32 ] : ~0ull;
            c2 = (lane + 64  < cnt) ? cand[lane + 64 ] : ~0ull;
            c3 = (lane + 96  < cnt) ? cand[lane + 96 ] : ~0ull;
            c4 = (lane + 128 < cnt) ? cand[lane + 128] : ~0ull;
            c5 = ~0ull;
            // Bose-Nelson sort-6 (ascending; u64 key = (d2, idx))
            ce(c0,c1); ce(c2,c3); ce(c4,c5);
            ce(c0,c2); ce(c3,c5); ce(c1,c4);
            ce(c0,c1); ce(c2,c3); ce(c4,c5);
            ce(c1,c2); ce(c3,c4); ce(c2,c3);

            unsigned hdb = (unsigned)(c0 >> 32);  // ~0ull head -> 0xffffffff (> any d2 bits)
#pragma unroll 1
            for (int r = 0; r < KCAP; r++) {
                unsigned m = redux_min_u32(hdb);
                unsigned tied = __ballot_sync(FULLMASK, hdb == m);
                int src;
                if ((tied & (tied - 1u)) == 0u) {
                    src = __ffs(tied) - 1;
                } else {
                    unsigned lw = (hdb == m) ? (unsigned)c0 : 0xffffffffu;
                    unsigned mi = redux_min_u32(lw);
                    src = __ffs(__ballot_sync(FULLMASK, lw == mi)) - 1;
                }
                u64 win = __shfl_sync(FULLMASK, c0, src);
                if (lane == r) mykey = win;
                bool pop = (lane == src);
                c0 = pop ? c1 : c0;
                c1 = pop ? c2 : c1;
                c2 = pop ? c3 : c2;
                c3 = pop ? c4 : c3;
                c4 = pop ? c5 : c4;
                c5 = pop ? ~0ull : c5;
                hdb = (unsigned)(c0 >> 32);
            }
        }
        float seld2  = __uint_as_float((unsigned)(mykey >> 32));
        int   selidx = (int)(mykey & 0xffffffffu);
        if (lane >= nsel) { seld2 = 3.4e38f; selidx = 0; }

        bool v0 = (lane < nsel) && (seld2 <= R0SQ);
        int  c0cnt = __popc(__ballot_sync(FULLMASK, v0));
        float coeff = 0.0f;
        if (v0)          coeff += sw0v / (float)(c0cnt > 1 ? c0cnt : 1);
        if (lane < nsel) coeff += sw1v / (float)(nsel  > 1 ? nsel  : 1);

        // prefetch this neighbor's feature row (64 floats = 2 lines)
        const float* frowf = rnd + (size_t)(bix * NL + selidx) * H;
        asm volatile("prefetch.global.L1 [%0];" :: "l"(frowf));
        asm volatile("prefetch.global.L1 [%0];" :: "l"(frowf + 32));

        // ---- layer 0: [yx,yy,qx,qy] @ W0 + b0 -> gelu -> h0[64] ----
        float h0[64];
        {
            float2 yc = __ldg(latf2 + selidx);
            u64 yx2 = pk2(yc.x, yc.x), yy2 = pk2(yc.y, yc.y);
            u64 qx2 = pk2(qx, qx),     qy2 = pk2(qy, qy);
            const u64* w0r0 = (const u64*)(sm + OFF_WE0);
            const u64* w0r1 = (const u64*)(sm + OFF_WE0 + 64);
            const u64* w0r2 = (const u64*)(sm + OFF_WE0 + 128);
            const u64* w0r3 = (const u64*)(sm + OFF_WE0 + 192);
            const u64* b0p  = (const u64*)(sm + OFF_BE0);
#pragma unroll
            for (int jp = 0; jp < 32; jp++) {
                u64 t = b0p[jp];
                t = f2fma(yx2, w0r0[jp], t);
                t = f2fma(yy2, w0r1[jp], t);
                t = f2fma(qx2, w0r2[jp], t);
                t = f2fma(qy2, w0r3[jp], t);
                float a, b; upk2(t, a, b);
                h0[2*jp]   = gelu_f(a);
                h0[2*jp+1] = gelu_f(b);
            }
        }

        // ---- layer 1: h0 @ W1 + b1 -> gelu -> h1[64]  (channel-tiled x2) ----
        float h1[64];
        {
            const ulonglong2* w1 = (const ulonglong2*)(sm + OFF_W1);
#pragma unroll
            for (int t = 0; t < 2; t++) {
                u64 a[16];
                const u64* b1p = (const u64*)(sm + OFF_BE1) + 8*t;
#pragma unroll
                for (int p = 0; p < 16; p++) a[p] = b1p[p];
#pragma unroll 4
                for (int i = 0; i < 64; i++) {
                    u64 hh = pk2(h0[i], h0[i]);
                    const ulonglong2* row = w1 + i*16 + t*8;
#pragma unroll
                    for (int j2 = 0; j2 < 8; j2++) {
                        ulonglong2 w = row[j2];
                        a[2*j2]   = f2fma(hh, w.x, a[2*j2]);
                        a[2*j2+1] = f2fma(hh, w.y, a[2*j2+1]);
                    }
                }
#pragma unroll
                for (int p = 0; p < 16; p++) {
                    float x, y; upk2(a[p], x, y);
                    h1[32*t + 2*p]   = gelu_f(x);
                    h1[32*t + 2*p+1] = gelu_f(y);
                }
            }
        }

        // ---- layer 2 + f(y)*coeff + neighbor-reduce + projection accumulate ----
        u64 hp2[4];
#pragma unroll
        for (int k = 0; k < 4; k++) hp2[k] = bp0p[k];
        {
            u64 cc = pk2(coeff, coeff);
            const float4* frow = (const float4*)frowf;
            const ulonglong2* w2 = (const ulonglong2*)(sm + OFF_W2);
#pragma unroll
            for (int t = 0; t < 2; t++) {
                u64 a[16];
                const u64* b2p = (const u64*)(sm + OFF_BE2) + 8*t;
#pragma unroll
                for (int p = 0; p < 16; p++) a[p] = b2p[p];
#pragma unroll 4
                for (int i = 0; i < 64; i++) {
                    u64 hh = pk2(h1[i], h1[i]);
                    const ulonglong2* row = w2 + i*16 + t*8;
#pragma unroll
                    for (int j2 = 0; j2 < 8; j2++) {
                        ulonglong2 w = row[j2];
                        a[2*j2]   = f2fma(hh, w.x, a[2*j2]);
                        a[2*j2+1] = f2fma(hh, w.y, a[2*j2+1]);
                    }
                }
#pragma unroll
                for (int p2 = 0; p2 < 8; p2++) {
                    float4 f4 = __ldg(frow + 8*t + p2);
                    u64 rA = f2mul(a[2*p2],   f2mul(pk2(f4.x, f4.y), cc));
                    u64 rB = f2mul(a[2*p2+1], f2mul(pk2(f4.z, f4.w), cc));
                    rA = wsum2(rA);                       // decoded channels chb, chb+1
                    rB = wsum2(rB);                       // decoded channels chb+2, chb+3
                    float dv0, dv1, dv2, dv3;
                    upk2(rA, dv0, dv1); upk2(rB, dv2, dv3);
                    int chb = 32*t + 4*p2;
                    float dvs[4] = {dv0, dv1, dv2, dv3};
#pragma unroll
                    for (int rr = 0; rr < 4; rr++) {
                        u64 dd = pk2(dvs[rr], dvs[rr]);
                        const ulonglong2* wr =
                            (const ulonglong2*)(wp0 + (size_t)(chb+rr)*PH + 8*lane);
                        ulonglong2 wa = wr[0], wb = wr[1];
                        hp2[0] = f2fma(dd, wa.x, hp2[0]);
                        hp2[1] = f2fma(dd, wa.y, hp2[1]);
                        hp2[2] = f2fma(dd, wb.x, hp2[2]);
                        hp2[3] = f2fma(dd, wb.y, hp2[3]);
                    }
                }
            }
        }

        // ---- projection tail: gelu -> [256 -> 3] ----
        float hpf[8];
#pragma unroll
        for (int k = 0; k < 4; k++) {
            float a, b; upk2(hp2[k], a, b);
            hpf[2*k]   = gelu_f(a);
            hpf[2*k+1] = gelu_f(b);
        }
        float o0, o1, o2;
#pragma unroll
        for (int c = 0; c < COUT; c++) {
            const float4* w = (const float4*)(sm + OFF_WP1T + c*PH + 8*lane);
            float4 w0v = w[0], w1v = w[1];
            float oc;
            oc = hpf[0]*w0v.x;
            oc = fmaf(hpf[1], w0v.y, oc);
            oc = fmaf(hpf[2], w0v.z, oc);
            oc = fmaf(hpf[3], w0v.w, oc);
            oc = fmaf(hpf[4], w1v.x, oc);
            oc = fmaf(hpf[5], w1v.y, oc);
            oc = fmaf(hpf[6], w1v.z, oc);
            oc = fmaf(hpf[7], w1v.w, oc);
            if (c == 0) o0 = oc; else if (c == 1) o1 = oc; else o2 = oc;
        }
        // reduce o0,o1 packed + o2 scalar
        u64 o01 = wsum2(pk2(o0, o1));
#pragma unroll
        for (int off = 16; off > 0; off >>= 1)
            o2 += __shfl_xor_sync(FULLMASK, o2, off);
        if (lane == 0) {
            float a, b; upk2(o01, a, b);
            out[q*COUT + 0] = a  + sm[OFF_BP1 + 0];
            out[q*COUT + 1] = b  + sm[OFF_BP1 + 1];
            out[q*COUT + 2] = o2 + sm[OFF_BP1 + 2];
        }
        __syncwarp();
    }
}

extern "C" void kernel_launch(void* const* d_in, const int* in_sizes, int n_in,
                              void* d_out, int out_size) {
    const float* lat  = (const float*)d_in[0];
    const float* rnd  = (const float*)d_in[1];
    const float* qry  = (const float*)d_in[2];
    const float* we0  = (const float*)d_in[3];
    const float* be0  = (const float*)d_in[4];
    const float* we1  = (const float*)d_in[5];
    const float* be1  = (const float*)d_in[6];
    const float* we2  = (const float*)d_in[7];
    const float* be2  = (const float*)d_in[8];
    const float* wsw0 = (const float*)d_in[9];
    const float* bsw0 = (const float*)d_in[10];
    const float* wsw1 = (const float*)d_in[11];
    const float* bsw1 = (const float*)d_in[12];
    const float* wp0  = (const float*)d_in[13];
    const float* bp0  = (const float*)d_in[14];
    const float* wp1  = (const float*)d_in[15];
    const float* bp1  = (const float*)d_in[16];
    float* out = (float*)d_out;

    cudaFuncSetAttribute(magno_kernel, cudaFuncAttributeMaxDynamicSharedMemorySize, SMEM_BYTES);
    magno_kernel<<<NBLOCK, THREADS, SMEM_BYTES>>>(
        lat, rnd, qry, we0, be0, we1, be1, we2, be2,
        wsw0, bsw0, wsw1, bsw1, wp0, bp0, wp1, bp1, out);
}